// round 15
// baseline (speedup 1.0000x reference)
#include <cuda_runtime.h>
#include <cstdint>

#define B_  64
#define T_  120
#define P_  25
#define D_  128
#define TILES 1536        // (b, 5-t group); 125 rows padded to 128
#define ROWS_V 125
#define HS 132            // hy stride in floats (conflict-free A loads)
#define NT_ 1024          // threads per CTA (32 warps)
#define XSTR 384000       // per-b stride in x/out (3200*120)

// ---- smem byte offsets ----
#define SO_W   0                    // packed W fragments (float4): 131072
#define SO_HY  131072               // 128*132*4 = 67584
#define SO_DS  198656               // 5*625*4 = 12500
#define SO_KN  211156               // 125 uchar4 = 500
#define SO_PS  213184               // 512*4 = 2048
#define SO_PQ  215232               // 512*4 = 2048
#define SO_BB  217280               // 256*4
#define SO_GG  218304               // 256*4
#define SO_BE  219328               // 256*4
#define SMEM_MAIN 220352

static __device__ __forceinline__ uint32_t f2tf32(float x){
    uint32_t u; asm("cvt.rna.tf32.f32 %0, %1;" : "=r"(u) : "f"(x)); return u;
}
static __device__ __forceinline__ void mma8(float* c, uint32_t a0, uint32_t a1,
                                            uint32_t a2, uint32_t a3,
                                            uint32_t b0, uint32_t b1){
    asm volatile("mma.sync.aligned.m16n8k8.row.col.f32.tf32.tf32.f32 "
        "{%0,%1,%2,%3}, {%4,%5,%6,%7}, {%8,%9}, {%0,%1,%2,%3};"
        : "+f"(c[0]), "+f"(c[1]), "+f"(c[2]), "+f"(c[3])
        : "r"(a0), "r"(a1), "r"(a2), "r"(a3), "r"(b0), "r"(b1));
}

// ---------------------------------------------------------------------------
// Single fused kernel. 32 warps: 8 row-blocks (16 rows) x 4 col-quarters.
// GEMM uses mma fragment ownership (2-col); epilogue uses float4 ownership:
// thread (cq,qc) owns cols cb+16j+4qc..+3 (j=0,1) of rows R0,R1.
// ---------------------------------------------------------------------------
__global__ __launch_bounds__(NT_, 1)
void k_main(const float* __restrict__ x,
            const float* __restrict__ dist_g,
            const float* __restrict__ w_g,
            const float* __restrict__ bias_g,
            const float* __restrict__ gamma_g,
            const float* __restrict__ beta_g,
            float* __restrict__ out)
{
    extern __shared__ char smc[];
    float*  Ws  = (float*)(smc + SO_W);
    float*  hy  = (float*)(smc + SO_HY);
    float*  ds  = (float*)(smc + SO_DS);
    uchar4* knc = (uchar4*)(smc + SO_KN);
    float*  ps  = (float*)(smc + SO_PS);
    float*  pq  = (float*)(smc + SO_PQ);
    float*  bb  = (float*)(smc + SO_BB);
    float*  gg  = (float*)(smc + SO_GG);
    float*  be  = (float*)(smc + SO_BE);

    const int tid  = threadIdx.x;
    const int warp = tid >> 5, lane = tid & 31;
    const int qr = lane >> 2;          // 0..7
    const int qc = lane & 3;           // 0..3
    const int m  = warp & 7;           // row-block
    const int cq = warp >> 3;          // col quarter 0..3
    const int cb = cq * 32;
    const int R0 = m * 16 + qr;        // < 120, always valid
    const int R1 = R0 + 8;             // may be pad row
    const bool v1 = (R1 < ROWS_V);

    // ---- pack both weight matrices into fragment-order float4s ----
    for (int i = tid; i < 2 * D_ * D_; i += NT_) {
        int l = i >> 14, k = (i >> 7) & 127, n = i & 127;
        int kt = k >> 3, c = k & 3, hi = (k >> 2) & 1;
        int g = n & 7, np8 = n >> 3;
        int q4 = np8 >> 2, j = (np8 >> 1) & 1, od = np8 & 1;
        ((uint32_t*)Ws)[(((((l*16 + kt)*8 + q4*2 + j)*32 + g*4 + c) << 2)
                         + ((od << 1) | hi))] = f2tf32(w_g[i]);
    }
    if (tid < 256) {
        bb[tid] = bias_g[tid]; gg[tid] = gamma_g[tid]; be[tid] = beta_g[tid];
    }
    __syncthreads();

    float hres[2][2][4];   // fp32 residual h: [row R0/R1][span j][4 cols]
    float acc[4][4];       // mma accumulators / z scratch

    for (int tile = blockIdx.x; tile < TILES; tile += gridDim.x) {
        const int b  = tile / 24;
        const int t0 = (tile - b * 24) * 5;
        const float* xb = x + (size_t)b * XSTR + t0;
        float* ob = out + (size_t)b * XSTR + t0;

        // ---- stage x -> hy (fp32), (pd, t)-ordered for 20B gmem chunks ----
        for (int i = tid; i < 16000; i += NT_) {
            int pd = i / 5, tl = i - pd * 5;
            int p = pd >> 7, col = pd & 127;
            hy[(tl * 25 + p) * HS + col] = xb[(size_t)pd * 120 + tl];
        }
        for (int i = tid; i < 5 * P_ * P_; i += NT_)
            ds[i] = dist_g[(size_t)tile * 3125 + i];
        __syncthreads();

        // ---- exact residual (float4 ownership) + in-place tf32 convert ----
#pragma unroll
        for (int j = 0; j < 2; ++j) {
            int col = cb + 16*j + 4*qc;
            float4 a = *(const float4*)&hy[R0 * HS + col];
            hres[0][j][0]=a.x; hres[0][j][1]=a.y; hres[0][j][2]=a.z; hres[0][j][3]=a.w;
            *(uint4*)&((uint32_t*)hy)[R0 * HS + col] =
                make_uint4(f2tf32(a.x), f2tf32(a.y), f2tf32(a.z), f2tf32(a.w));
            if (v1) {
                float4 bv = *(const float4*)&hy[R1 * HS + col];
                hres[1][j][0]=bv.x; hres[1][j][1]=bv.y; hres[1][j][2]=bv.z; hres[1][j][3]=bv.w;
                *(uint4*)&((uint32_t*)hy)[R1 * HS + col] =
                    make_uint4(f2tf32(bv.x), f2tf32(bv.y), f2tf32(bv.z), f2tf32(bv.w));
            } else {
                hres[1][j][0]=0.f; hres[1][j][1]=0.f; hres[1][j][2]=0.f; hres[1][j][3]=0.f;
                *(uint4*)&((uint32_t*)hy)[R1 * HS + col] = make_uint4(0u,0u,0u,0u);
            }
        }

        // kNN (4 smallest, self excluded), packed uchar4
        if (tid < ROWS_V) {
            const int p = tid % 25;
            const float* dp = ds + (tid / 25) * 625 + p * 25;
            float bv0 = 1e30f, bv1 = 1e30f, bv2 = 1e30f, bv3 = 1e30f;
            int bi0 = 0, bi1 = 0, bi2 = 0, bi3 = 0;
            for (int q = 0; q < 25; ++q) {
                if (q == p) continue;
                float dv = dp[q];
                if (dv < bv3) {
                    bv3 = dv; bi3 = q;
                    if (bv3 < bv2) { float t=bv3; bv3=bv2; bv2=t; int ti=bi3; bi3=bi2; bi2=ti; }
                    if (bv2 < bv1) { float t=bv2; bv2=bv1; bv1=t; int ti=bi2; bi2=bi1; bi1=ti; }
                    if (bv1 < bv0) { float t=bv1; bv1=bv0; bv0=t; int ti=bi1; bi1=bi0; bi0=ti; }
                }
            }
            const int base = (tid / 25) * 25;
            knc[tid] = make_uchar4((unsigned char)(base + bi0),
                                   (unsigned char)(base + bi1),
                                   (unsigned char)(base + bi2),
                                   (unsigned char)(base + bi3));
        }
        __syncthreads();   // hy fully tf32 + kn ready

#pragma unroll
        for (int l = 0; l < 2; ++l) {
            // ---- y = h @ W_l  (warp: 16 rows x 32 cols; fragment ownership) ----
#pragma unroll
            for (int nt = 0; nt < 4; ++nt)
#pragma unroll
                for (int j = 0; j < 4; ++j) acc[nt][j] = 0.f;

            const uint32_t* hyu = (const uint32_t*)hy;
            const float4* wf = (const float4*)Ws
                + (size_t)l*16*8*32 + cq*2*32 + qr*4 + qc;
#pragma unroll
            for (int kt = 0; kt < 16; ++kt) {
                uint32_t a0 = hyu[R0 * HS + 8*kt + qc];
                uint32_t a1 = hyu[R1 * HS + 8*kt + qc];
                uint32_t a2 = hyu[R0 * HS + 8*kt + qc + 4];
                uint32_t a3 = hyu[R1 * HS + 8*kt + qc + 4];
                const float4* wk = wf + kt*8*32;
#pragma unroll
                for (int j = 0; j < 2; ++j) {
                    float4 bv = wk[j*32];
                    mma8(acc[2*j],     a0, a1, a2, a3,
                         __float_as_uint(bv.x), __float_as_uint(bv.y));
                    mma8(acc[2*j + 1], a0, a1, a2, a3,
                         __float_as_uint(bv.z), __float_as_uint(bv.w));
                }
            }
            __syncthreads();   // all A reads done; hy becomes y buffer

            // stage y into hy (fragment ownership)
#pragma unroll
            for (int nt = 0; nt < 4; ++nt) {
                int col = cb + 8*nt + 2*qc;
                *(float2*)&hy[R0 * HS + col] = make_float2(acc[nt][0], acc[nt][1]);
                *(float2*)&hy[R1 * HS + col] = make_float2(acc[nt][2], acc[nt][3]);
            }
            __syncthreads();   // y visible CTA-wide

            // ---- gather (float4 ownership): (self+4nb)/5 + bias + relu ----
            const uchar4 k0 = knc[R0];
            const uchar4 k1 = knc[v1 ? R1 : 0];
            float S0 = 0.f, Q0 = 0.f, S1 = 0.f, Q1 = 0.f;
#pragma unroll
            for (int j = 0; j < 2; ++j) {
                int col = cb + 16*j + 4*qc;
                float4 bi4 = *(const float4*)&bb[l*128 + col];
                {
                    float4 s  = *(const float4*)&hy[R0*HS + col];
                    float4 e0 = *(const float4*)&hy[k0.x*HS + col];
                    float4 e1 = *(const float4*)&hy[k0.y*HS + col];
                    float4 e2 = *(const float4*)&hy[k0.z*HS + col];
                    float4 e3 = *(const float4*)&hy[k0.w*HS + col];
                    float z0 = fmaxf(fmaf(0.2f, s.x+e0.x+e1.x+e2.x+e3.x, bi4.x), 0.f);
                    float z1 = fmaxf(fmaf(0.2f, s.y+e0.y+e1.y+e2.y+e3.y, bi4.y), 0.f);
                    float z2 = fmaxf(fmaf(0.2f, s.z+e0.z+e1.z+e2.z+e3.z, bi4.z), 0.f);
                    float z3 = fmaxf(fmaf(0.2f, s.w+e0.w+e1.w+e2.w+e3.w, bi4.w), 0.f);
                    acc[j][0]=z0; acc[j][1]=z1; acc[j][2]=z2; acc[j][3]=z3;
                    S0 += (z0+z1) + (z2+z3);
                    Q0 = fmaf(z0,z0,Q0); Q0 = fmaf(z1,z1,Q0);
                    Q0 = fmaf(z2,z2,Q0); Q0 = fmaf(z3,z3,Q0);
                }
                {
                    float4 s  = *(const float4*)&hy[R1*HS + col];
                    float4 f0 = *(const float4*)&hy[k1.x*HS + col];
                    float4 f1 = *(const float4*)&hy[k1.y*HS + col];
                    float4 f2 = *(const float4*)&hy[k1.z*HS + col];
                    float4 f3 = *(const float4*)&hy[k1.w*HS + col];
                    float z0 = fmaxf(fmaf(0.2f, s.x+f0.x+f1.x+f2.x+f3.x, bi4.x), 0.f);
                    float z1 = fmaxf(fmaf(0.2f, s.y+f0.y+f1.y+f2.y+f3.y, bi4.y), 0.f);
                    float z2 = fmaxf(fmaf(0.2f, s.z+f0.z+f1.z+f2.z+f3.z, bi4.z), 0.f);
                    float z3 = fmaxf(fmaf(0.2f, s.w+f0.w+f1.w+f2.w+f3.w, bi4.w), 0.f);
                    acc[2+j][0]=z0; acc[2+j][1]=z1; acc[2+j][2]=z2; acc[2+j][3]=z3;
                    S1 += (z0+z1) + (z2+z3);
                    Q1 = fmaf(z0,z0,Q1); Q1 = fmaf(z1,z1,Q1);
                    Q1 = fmaf(z2,z2,Q1); Q1 = fmaf(z3,z3,Q1);
                }
            }
            // quad-reduce -> 32-col partials; combine 4 quarters via smem
            S0 += __shfl_xor_sync(0xffffffffu, S0, 1); S0 += __shfl_xor_sync(0xffffffffu, S0, 2);
            Q0 += __shfl_xor_sync(0xffffffffu, Q0, 1); Q0 += __shfl_xor_sync(0xffffffffu, Q0, 2);
            S1 += __shfl_xor_sync(0xffffffffu, S1, 1); S1 += __shfl_xor_sync(0xffffffffu, S1, 2);
            Q1 += __shfl_xor_sync(0xffffffffu, Q1, 1); Q1 += __shfl_xor_sync(0xffffffffu, Q1, 2);
            if (qc == 0) {
                ps[cq*128 + R0] = S0; pq[cq*128 + R0] = Q0;
                ps[cq*128 + R1] = S1; pq[cq*128 + R1] = Q1;
            }
            __syncthreads();   // partials visible; all gather reads done
            float Sa = ps[R0] + ps[128 + R0] + ps[256 + R0] + ps[384 + R0];
            float Qa = pq[R0] + pq[128 + R0] + pq[256 + R0] + pq[384 + R0];
            float Sb = ps[R1] + ps[128 + R1] + ps[256 + R1] + ps[384 + R1];
            float Qb = pq[R1] + pq[128 + R1] + pq[256 + R1] + pq[384 + R1];
            float mu0 = Sa * (1.f/128.f), var0 = Qa * (1.f/128.f) - mu0*mu0;
            float mu1 = Sb * (1.f/128.f), var1 = Qb * (1.f/128.f) - mu1*mu1;
            float rs0 = rsqrtf(var0 + 1e-5f), rs1 = rsqrtf(var1 + 1e-5f);
#pragma unroll
            for (int j = 0; j < 2; ++j) {
                int col = cb + 16*j + 4*qc;
                float4 g4 = *(const float4*)&gg[l*128 + col];
                float4 b4 = *(const float4*)&be[l*128 + col];
                hres[0][j][0] += (acc[j][0] - mu0) * rs0 * g4.x + b4.x;
                hres[0][j][1] += (acc[j][1] - mu0) * rs0 * g4.y + b4.y;
                hres[0][j][2] += (acc[j][2] - mu0) * rs0 * g4.z + b4.z;
                hres[0][j][3] += (acc[j][3] - mu0) * rs0 * g4.w + b4.w;
                hres[1][j][0] += (acc[2+j][0] - mu1) * rs1 * g4.x + b4.x;
                hres[1][j][1] += (acc[2+j][1] - mu1) * rs1 * g4.y + b4.y;
                hres[1][j][2] += (acc[2+j][2] - mu1) * rs1 * g4.z + b4.z;
                hres[1][j][3] += (acc[2+j][3] - mu1) * rs1 * g4.w + b4.w;
            }

            if (l == 0) {
                // store h1 (tf32) as next layer's A; keep pad rows zero
#pragma unroll
                for (int j = 0; j < 2; ++j) {
                    int col = cb + 16*j + 4*qc;
                    *(uint4*)&((uint32_t*)hy)[R0*HS + col] =
                        make_uint4(f2tf32(hres[0][j][0]), f2tf32(hres[0][j][1]),
                                   f2tf32(hres[0][j][2]), f2tf32(hres[0][j][3]));
                    *(uint4*)&((uint32_t*)hy)[R1*HS + col] = v1
                        ? make_uint4(f2tf32(hres[1][j][0]), f2tf32(hres[1][j][1]),
                                     f2tf32(hres[1][j][2]), f2tf32(hres[1][j][3]))
                        : make_uint4(0u,0u,0u,0u);
                }
                __syncthreads();   // h1 complete before next-layer GEMM
            } else {
                // stage final h (fp32) into hy for transposed writeback
#pragma unroll
                for (int j = 0; j < 2; ++j) {
                    int col = cb + 16*j + 4*qc;
                    *(float4*)&hy[R0*HS + col] =
                        make_float4(hres[0][j][0], hres[0][j][1],
                                    hres[0][j][2], hres[0][j][3]);
                    if (v1)
                        *(float4*)&hy[R1*HS + col] =
                            make_float4(hres[1][j][0], hres[1][j][1],
                                        hres[1][j][2], hres[1][j][3]);
                }
                __syncthreads();   // writeback reads cross-m rows
            }
        }

        // ---- writeback: hy -> out, (pd, t)-ordered ----
        for (int i = tid; i < 16000; i += NT_) {
            int pd = i / 5, tl = i - pd * 5;
            int p = pd >> 7, col = pd & 127;
            ob[(size_t)pd * 120 + tl] = hy[(tl * 25 + p) * HS + col];
        }
        __syncthreads();   // out reads done before next tile restages hy
    }
}

// ---------------------------------------------------------------------------
extern "C" void kernel_launch(void* const* d_in, const int* in_sizes, int n_in,
                              void* d_out, int out_size)
{
    const float* x     = (const float*)d_in[0];
    const float* dist  = (const float*)d_in[1];
    const float* w     = (const float*)d_in[2];
    const float* bias  = (const float*)d_in[3];
    const float* gamma = (const float*)d_in[4];
    const float* beta  = (const float*)d_in[5];
    float* out = (float*)d_out;

    cudaFuncSetAttribute(k_main, cudaFuncAttributeMaxDynamicSharedMemorySize,
                         SMEM_MAIN);

    int sms = 148;
    cudaDeviceGetAttribute(&sms, cudaDevAttrMultiProcessorCount, 0);

    k_main<<<sms, NT_, SMEM_MAIN>>>(x, dist, w, bias, gamma, beta, out);
}

// round 17
// speedup vs baseline: 1.4645x; 1.4645x over previous
#include <cuda_runtime.h>
#include <cstdint>

#define B_  64
#define T_  120
#define P_  25
#define D_  128
#define TILES 1536        // (b, 5-t group); 125 rows padded to 128
#define ROWS_V 125
#define HS 132            // hy stride in floats (conflict-free A loads)
#define NT_ 1024          // threads per CTA (32 warps)
#define XSTR 384000       // per-b stride in x/out (3200*120)

// ---- smem byte offsets ----
#define SO_W   0                    // packed W fragments (float4): 131072
#define SO_HY  131072               // 128*132*4 = 67584
#define SO_DS  198656               // 5*625*4 = 12500
#define SO_KN  211156               // 125 uchar4 = 500
#define SO_PS  213184               // 512*4 = 2048
#define SO_PQ  215232               // 512*4 = 2048
#define SO_BB  217280               // 256*4
#define SO_GG  218304               // 256*4
#define SO_BE  219328               // 256*4
#define SMEM_MAIN 220352

static __device__ __forceinline__ uint32_t f2tf32(float x){
    uint32_t u; asm("cvt.rna.tf32.f32 %0, %1;" : "=r"(u) : "f"(x)); return u;
}
static __device__ __forceinline__ void mma8(float* c, uint32_t a0, uint32_t a1,
                                            uint32_t a2, uint32_t a3,
                                            uint32_t b0, uint32_t b1){
    asm volatile("mma.sync.aligned.m16n8k8.row.col.f32.tf32.tf32.f32 "
        "{%0,%1,%2,%3}, {%4,%5,%6,%7}, {%8,%9}, {%0,%1,%2,%3};"
        : "+f"(c[0]), "+f"(c[1]), "+f"(c[2]), "+f"(c[3])
        : "r"(a0), "r"(a1), "r"(a2), "r"(a3), "r"(b0), "r"(b1));
}
// m-group barrier: the 4 warps {m, m+8, m+16, m+24} (128 threads), ids 1..8
#define BARM() asm volatile("bar.sync %0, 128;" :: "r"(mbid) : "memory")

// ---------------------------------------------------------------------------
// Single fused kernel. 32 warps: 8 row-blocks (16 rows) x 4 col-quarters.
// ---------------------------------------------------------------------------
__global__ __launch_bounds__(NT_, 1)
void k_main(const float* __restrict__ x,
            const float* __restrict__ dist_g,
            const float* __restrict__ w_g,
            const float* __restrict__ bias_g,
            const float* __restrict__ gamma_g,
            const float* __restrict__ beta_g,
            float* __restrict__ out)
{
    extern __shared__ char smc[];
    float*  Ws  = (float*)(smc + SO_W);
    float*  hy  = (float*)(smc + SO_HY);
    float*  ds  = (float*)(smc + SO_DS);
    uchar4* knc = (uchar4*)(smc + SO_KN);
    float*  ps  = (float*)(smc + SO_PS);
    float*  pq  = (float*)(smc + SO_PQ);
    float*  bb  = (float*)(smc + SO_BB);
    float*  gg  = (float*)(smc + SO_GG);
    float*  be  = (float*)(smc + SO_BE);

    const int tid  = threadIdx.x;
    const int warp = tid >> 5, lane = tid & 31;
    const int qr = lane >> 2;          // 0..7
    const int qc = lane & 3;           // 0..3
    const int m  = warp & 7;           // row-block
    const int mbid = 1 + m;            // named barrier id for this m-group
    const int cq = warp >> 3;          // col quarter 0..3
    const int cb = cq * 32;
    const int R0 = m * 16 + qr;        // < 120, always valid
    const int R1 = R0 + 8;             // may be pad row
    const bool v1 = (R1 < ROWS_V);

    // ---- pack both weight matrices into fragment-order float4s ----
    // float4 idx = ((l*16+kt)*8 + q4*2 + j)*32 + qr*4 + c, components:
    //   x = W[8kt+c][8*(8q4... )], covering n = 8*(4q4+2j+od)+g for hi=0/1.
    for (int i = tid; i < 2 * D_ * D_; i += NT_) {
        int l = i >> 14, k = (i >> 7) & 127, n = i & 127;
        int kt = k >> 3, c = k & 3, hi = (k >> 2) & 1;
        int g = n & 7, np8 = n >> 3;
        int q4 = np8 >> 2, j = (np8 >> 1) & 1, od = np8 & 1;
        ((uint32_t*)Ws)[(((((l*16 + kt)*8 + q4*2 + j)*32 + g*4 + c) << 2)
                         + ((od << 1) | hi))] = f2tf32(w_g[i]);
    }
    if (tid < 256) {
        bb[tid] = bias_g[tid]; gg[tid] = gamma_g[tid]; be[tid] = beta_g[tid];
    }
    __syncthreads();

    float hres[4][4];   // fp32 residual h (rows R0/R1, 8 owned cols)
    float acc[4][4];    // mma accumulators / z scratch

    for (int tile = blockIdx.x; tile < TILES; tile += gridDim.x) {
        const int b  = tile / 24;
        const int t0 = (tile - b * 24) * 5;
        const float* xb = x + (size_t)b * XSTR + t0;
        float* ob = out + (size_t)b * XSTR + t0;

        // ---- stage x -> hy (fp32), (pd, t)-ordered for 20B gmem chunks ----
        for (int i = tid; i < 16000; i += NT_) {
            int pd = i / 5, tl = i - pd * 5;
            int p = pd >> 7, col = pd & 127;
            hy[(tl * 25 + p) * HS + col] = xb[(size_t)pd * 120 + tl];
        }
        for (int i = tid; i < 5 * P_ * P_; i += NT_)
            ds[i] = dist_g[(size_t)tile * 3125 + i];
        __syncthreads();

        // ---- exact residual from hy + in-place tf32 convert ----
#pragma unroll
        for (int nt = 0; nt < 4; ++nt) {
            int col = cb + 8 * nt + 2 * qc;
            float2 a = *(const float2*)&hy[R0 * HS + col];
            hres[nt][0] = a.x; hres[nt][1] = a.y;
            *(uint2*)&((uint32_t*)hy)[R0 * HS + col] =
                make_uint2(f2tf32(a.x), f2tf32(a.y));
            if (v1) {
                float2 bv = *(const float2*)&hy[R1 * HS + col];
                hres[nt][2] = bv.x; hres[nt][3] = bv.y;
                *(uint2*)&((uint32_t*)hy)[R1 * HS + col] =
                    make_uint2(f2tf32(bv.x), f2tf32(bv.y));
            } else {
                hres[nt][2] = 0.f; hres[nt][3] = 0.f;
                *(uint2*)&((uint32_t*)hy)[R1 * HS + col] = make_uint2(0u, 0u);
            }
        }

        // kNN (4 smallest, self excluded), packed uchar4
        if (tid < ROWS_V) {
            const int p = tid % 25;
            const float* dp = ds + (tid / 25) * 625 + p * 25;
            float bv0 = 1e30f, bv1 = 1e30f, bv2 = 1e30f, bv3 = 1e30f;
            int bi0 = 0, bi1 = 0, bi2 = 0, bi3 = 0;
            for (int q = 0; q < 25; ++q) {
                if (q == p) continue;
                float dv = dp[q];
                if (dv < bv3) {
                    bv3 = dv; bi3 = q;
                    if (bv3 < bv2) { float t=bv3; bv3=bv2; bv2=t; int ti=bi3; bi3=bi2; bi2=ti; }
                    if (bv2 < bv1) { float t=bv2; bv2=bv1; bv1=t; int ti=bi2; bi2=bi1; bi1=ti; }
                    if (bv1 < bv0) { float t=bv1; bv1=bv0; bv0=t; int ti=bi1; bi1=bi0; bi0=ti; }
                }
            }
            const int base = (tid / 25) * 25;
            knc[tid] = make_uchar4((unsigned char)(base + bi0),
                                   (unsigned char)(base + bi1),
                                   (unsigned char)(base + bi2),
                                   (unsigned char)(base + bi3));
        }
        __syncthreads();   // hy fully tf32 + kn ready

#pragma unroll
        for (int l = 0; l < 2; ++l) {
            // ---- y = h @ W_l  (warp: 16 rows x 32 cols) ----
#pragma unroll
            for (int nt = 0; nt < 4; ++nt)
#pragma unroll
                for (int j = 0; j < 4; ++j) acc[nt][j] = 0.f;

            const uint32_t* hyu = (const uint32_t*)hy;
            const float4* wf = (const float4*)Ws
                + (size_t)l*16*8*32 + cq*2*32 + qr*4 + qc;
#pragma unroll
            for (int kt = 0; kt < 16; ++kt) {
                uint32_t a0 = hyu[R0 * HS + 8*kt + qc];
                uint32_t a1 = hyu[R1 * HS + 8*kt + qc];
                uint32_t a2 = hyu[R0 * HS + 8*kt + qc + 4];
                uint32_t a3 = hyu[R1 * HS + 8*kt + qc + 4];
                const float4* wk = wf + kt*8*32;
#pragma unroll
                for (int j = 0; j < 2; ++j) {
                    float4 bv = wk[j*32];
                    mma8(acc[2*j],     a0, a1, a2, a3,
                         __float_as_uint(bv.x), __float_as_uint(bv.y));
                    mma8(acc[2*j + 1], a0, a1, a2, a3,
                         __float_as_uint(bv.z), __float_as_uint(bv.w));
                }
            }
            // A rows of block m are written only by warps (m,*): m-local WAR
            BARM();

            // stage y into hy
#pragma unroll
            for (int nt = 0; nt < 4; ++nt) {
                int col = cb + 8*nt + 2*qc;
                *(float2*)&hy[R0 * HS + col] = make_float2(acc[nt][0], acc[nt][1]);
                *(float2*)&hy[R1 * HS + col] = make_float2(acc[nt][2], acc[nt][3]);
            }
            __syncthreads();   // y visible CTA-wide (gather reads cross-m rows)

            // gather (self + 4 nb)/5 + bias + relu; partial LN stats
            const uchar4 k0 = knc[R0];
            const uchar4 k1 = knc[v1 ? R1 : 0];
            const int n00 = k0.x, n01 = k0.y, n02 = k0.z, n03 = k0.w;
            const int n10 = k1.x, n11 = k1.y, n12 = k1.z, n13 = k1.w;
            float S0 = 0.f, Q0 = 0.f, S1 = 0.f, Q1 = 0.f;
#pragma unroll
            for (int nt = 0; nt < 4; ++nt) {
                int col = cb + 8*nt + 2*qc;
                float2 bi2v = *(const float2*)&bb[l*128 + col];
                float2 e0 = *(const float2*)&hy[n00*HS + col];
                float2 e1 = *(const float2*)&hy[n01*HS + col];
                float2 e2 = *(const float2*)&hy[n02*HS + col];
                float2 e3 = *(const float2*)&hy[n03*HS + col];
                float z0 = fmaxf(fmaf(0.2f, acc[nt][0]+e0.x+e1.x+e2.x+e3.x, bi2v.x), 0.f);
                float z1 = fmaxf(fmaf(0.2f, acc[nt][1]+e0.y+e1.y+e2.y+e3.y, bi2v.y), 0.f);
                float2 f0 = *(const float2*)&hy[n10*HS + col];
                float2 f1 = *(const float2*)&hy[n11*HS + col];
                float2 f2 = *(const float2*)&hy[n12*HS + col];
                float2 f3 = *(const float2*)&hy[n13*HS + col];
                float z2 = fmaxf(fmaf(0.2f, acc[nt][2]+f0.x+f1.x+f2.x+f3.x, bi2v.x), 0.f);
                float z3 = fmaxf(fmaf(0.2f, acc[nt][3]+f0.y+f1.y+f2.y+f3.y, bi2v.y), 0.f);
                acc[nt][0] = z0; acc[nt][1] = z1; acc[nt][2] = z2; acc[nt][3] = z3;
                S0 += z0 + z1; Q0 = fmaf(z0, z0, Q0); Q0 = fmaf(z1, z1, Q0);
                S1 += z2 + z3; Q1 = fmaf(z2, z2, Q1); Q1 = fmaf(z3, z3, Q1);
            }
            // quad-reduce -> 32-col partials; combine 4 quarters via smem
            S0 += __shfl_xor_sync(0xffffffffu, S0, 1); S0 += __shfl_xor_sync(0xffffffffu, S0, 2);
            Q0 += __shfl_xor_sync(0xffffffffu, Q0, 1); Q0 += __shfl_xor_sync(0xffffffffu, Q0, 2);
            S1 += __shfl_xor_sync(0xffffffffu, S1, 1); S1 += __shfl_xor_sync(0xffffffffu, S1, 2);
            Q1 += __shfl_xor_sync(0xffffffffu, Q1, 1); Q1 += __shfl_xor_sync(0xffffffffu, Q1, 2);
            if (qc == 0) {
                ps[cq*128 + R0] = S0; pq[cq*128 + R0] = Q0;
                ps[cq*128 + R1] = S1; pq[cq*128 + R1] = Q1;
            }
            __syncthreads();   // all gathers done CTA-wide + partials visible
            float Sa = ps[R0] + ps[128 + R0] + ps[256 + R0] + ps[384 + R0];
            float Qa = pq[R0] + pq[128 + R0] + pq[256 + R0] + pq[384 + R0];
            float Sb = ps[R1] + ps[128 + R1] + ps[256 + R1] + ps[384 + R1];
            float Qb = pq[R1] + pq[128 + R1] + pq[256 + R1] + pq[384 + R1];
            float mu0 = Sa * (1.f/128.f), var0 = Qa * (1.f/128.f) - mu0*mu0;
            float mu1 = Sb * (1.f/128.f), var1 = Qb * (1.f/128.f) - mu1*mu1;
            float rs0 = rsqrtf(var0 + 1e-5f), rs1 = rsqrtf(var1 + 1e-5f);
#pragma unroll
            for (int nt = 0; nt < 4; ++nt) {
                int col = cb + 8*nt + 2*qc;
                float2 g2 = *(const float2*)&gg[l*128 + col];
                float2 b2 = *(const float2*)&be[l*128 + col];
                hres[nt][0] += (acc[nt][0] - mu0) * rs0 * g2.x + b2.x;
                hres[nt][1] += (acc[nt][1] - mu0) * rs0 * g2.y + b2.y;
                hres[nt][2] += (acc[nt][2] - mu1) * rs1 * g2.x + b2.x;
                hres[nt][3] += (acc[nt][3] - mu1) * rs1 * g2.y + b2.y;
            }

            if (l == 0) {
                // store h1 (tf32) as next layer's A; keep pad rows zero
#pragma unroll
                for (int nt = 0; nt < 4; ++nt) {
                    int col = cb + 8*nt + 2*qc;
                    *(uint2*)&((uint32_t*)hy)[R0*HS + col] =
                        make_uint2(f2tf32(hres[nt][0]), f2tf32(hres[nt][1]));
                    *(uint2*)&((uint32_t*)hy)[R1*HS + col] = v1
                        ? make_uint2(f2tf32(hres[nt][2]), f2tf32(hres[nt][3]))
                        : make_uint2(0u, 0u);
                }
                // layer-2 A reads of block-m rows come only from warps (m,*)
                BARM();
            } else {
                // stage final h (fp32) into hy for transposed writeback
#pragma unroll
                for (int nt = 0; nt < 4; ++nt) {
                    int col = cb + 8*nt + 2*qc;
                    *(float2*)&hy[R0*HS + col] = make_float2(hres[nt][0], hres[nt][1]);
                    if (v1)
                        *(float2*)&hy[R1*HS + col] = make_float2(hres[nt][2], hres[nt][3]);
                }
                __syncthreads();   // writeback reads cross-m rows
            }
        }

        // ---- writeback: hy -> out, (pd, t)-ordered ----
        for (int i = tid; i < 16000; i += NT_) {
            int pd = i / 5, tl = i - pd * 5;
            int p = pd >> 7, col = pd & 127;
            ob[(size_t)pd * 120 + tl] = hy[(tl * 25 + p) * HS + col];
        }
        __syncthreads();   // out reads done before next tile restages hy
    }
}

// ---------------------------------------------------------------------------
extern "C" void kernel_launch(void* const* d_in, const int* in_sizes, int n_in,
                              void* d_out, int out_size)
{
    const float* x     = (const float*)d_in[0];
    const float* dist  = (const float*)d_in[1];
    const float* w     = (const float*)d_in[2];
    const float* bias  = (const float*)d_in[3];
    const float* gamma = (const float*)d_in[4];
    const float* beta  = (const float*)d_in[5];
    float* out = (float*)d_out;

    cudaFuncSetAttribute(k_main, cudaFuncAttributeMaxDynamicSharedMemorySize,
                         SMEM_MAIN);

    int sms = 148;
    cudaDeviceGetAttribute(&sms, cudaDevAttrMultiProcessorCount, 0);

    k_main<<<sms, NT_, SMEM_MAIN>>>(x, dist, w, bias, gamma, beta, out);
}